// round 9
// baseline (speedup 1.0000x reference)
#include <cuda_runtime.h>
#include <cuda_fp16.h>
#include <cstdint>
#include <cstddef>

// ---------------------------------------------------------------------------
constexpr int B_ = 4;
constexpr int N_ = 4096;
constexpr int K_ = 32;
constexpr int CPB = N_ * K_;              // 131072 columns per batch
constexpr int TPB = CPB / 128;            // 1024 full tiles per batch
constexpr int LDB = 68;                   // u32 stride per n-col of B tile

// ---------------------------------------------------------------------------
// Scratch: packed fp16 intermediates (B-fragment layout for direct cp.async)
// ---------------------------------------------------------------------------
__device__ uint32_t feat1p[B_][N_][32];                    //   2 MB
__device__ uint32_t g1p [(size_t)B_ * TPB * 128 * 32];     //  64 MB
__device__ uint32_t x1p [(size_t)B_ * TPB * 128 * 64];     // 128 MB
__device__ __half   y3h [(size_t)B_ * 128 * CPB];          // 128 MB

__device__ double g_sum  [3][B_][128];
__device__ double g_sq   [3][B_][128];
__device__ float  g_scale[3][B_][128];
__device__ float  g_shift[3][B_][128];

// ---------------------------------------------------------------------------
__device__ __forceinline__ uint32_t smem_to_u32(const void* p) {
    uint32_t a;
    asm("{ .reg .u64 t; cvta.to.shared.u64 t, %1; cvt.u32.u64 %0, t; }"
        : "=r"(a) : "l"(p));
    return a;
}
__device__ __forceinline__ void cp_async16(uint32_t dst, const void* src) {
    asm volatile("cp.async.cg.shared.global [%0], [%1], 16;" :: "r"(dst), "l"(src));
}
__device__ __forceinline__ void cp_async16_ca(uint32_t dst, const void* src) {
    asm volatile("cp.async.ca.shared.global [%0], [%1], 16;" :: "r"(dst), "l"(src));
}
#define CP_COMMIT() asm volatile("cp.async.commit_group;" ::: "memory")
#define CP_WAIT0()  asm volatile("cp.async.wait_group 0;" ::: "memory")

#define MMA_F16(d, a0, a1, a2, a3, b0, b1) \
    asm volatile("mma.sync.aligned.m16n8k16.row.col.f32.f16.f16.f32 " \
        "{%0,%1,%2,%3},{%4,%5,%6,%7},{%8,%9},{%0,%1,%2,%3};" \
        : "+f"((d)[0]), "+f"((d)[1]), "+f"((d)[2]), "+f"((d)[3]) \
        : "r"(a0), "r"(a1), "r"(a2), "r"(a3), "r"(b0), "r"(b1))

__device__ __forceinline__ uint32_t packh(float x0, float x1) {
    __half2 h = __float22half2_rn(make_float2(x0, x1));
    return *(uint32_t*)&h;
}

// ---------------------------------------------------------------------------
__global__ void zero_stats_k() {
    int t = blockIdx.x * blockDim.x + threadIdx.x;
    if (t < 3 * B_ * 128) {
        (&g_sum[0][0][0])[t] = 0.0;
        (&g_sq [0][0][0])[t] = 0.0;
    }
}

// ---------------------------------------------------------------------------
// feat1 = relu(W_feat @ feat + b): packed fp16 into feat1p + gn1 stats (ch<64)
// ---------------------------------------------------------------------------
__global__ void __launch_bounds__(256) feat1_k(const float* __restrict__ feat,
                                               const float* __restrict__ Wf,
                                               const float* __restrict__ bf) {
    __shared__ float Ws[64 * 128];
    __shared__ float Fs[128 * 32];
    const int b  = blockIdx.y;
    const int n0 = blockIdx.x * 32;
    const int tid = threadIdx.x;

    for (int idx = tid; idx < 64 * 128; idx += 256) Ws[idx] = Wf[idx];
    for (int idx = tid; idx < 128 * 32; idx += 256) {
        int c = idx >> 5, jj = idx & 31;
        Fs[idx] = feat[(size_t)(b * 128 + c) * N_ + n0 + jj];
    }
    __syncthreads();

    const int jj = tid & 31;
    const int w  = tid >> 5;
    float acc[8];
#pragma unroll
    for (int oi = 0; oi < 8; ++oi) acc[oi] = __ldg(bf + w * 8 + oi);
#pragma unroll 4
    for (int c = 0; c < 128; ++c) {
        float x = Fs[c * 32 + jj];
#pragma unroll
        for (int oi = 0; oi < 8; ++oi)
            acc[oi] = fmaf(Ws[(w * 8 + oi) * 128 + c], x, acc[oi]);
    }
#pragma unroll
    for (int oi = 0; oi < 8; ++oi) acc[oi] = fmaxf(acc[oi], 0.f);

#pragma unroll
    for (int oi = 0; oi < 8; ++oi) {
        float s = acc[oi], q = acc[oi] * acc[oi];
#pragma unroll
        for (int off = 16; off; off >>= 1) {
            s += __shfl_xor_sync(0xffffffffu, s, off);
            q += __shfl_xor_sync(0xffffffffu, q, off);
        }
        if (jj == 0) {
            atomicAdd(&g_sum[0][b][w * 8 + oi], (double)(32.0f * s));
            atomicAdd(&g_sq [0][b][w * 8 + oi], (double)(32.0f * q));
        }
    }
    uint4 pk;
    pk.x = packh(acc[0], acc[1]);
    pk.y = packh(acc[2], acc[3]);
    pk.z = packh(acc[4], acc[5]);
    pk.w = packh(acc[6], acc[7]);
    *(uint4*)&feat1p[b][n0 + jj][w * 4] = pk;
}

// ---------------------------------------------------------------------------
struct Ptrs {
    const float* X;
    const float* W;
    const float* bias;
    const int*   count;
    float*       out;
};

// All modes: 32x32 warp tiles (2 m-tiles), single fp16 A in registers.
// MODE 0: g1p = relu(W_grp@gf+b), 128-col tiles, warps 2(M) x 4(N)
// MODE 1: y3h = W_fo@gfo+b, 64-col tiles, warps 4 x 2
// MODE 2: x1p = relu(Wwc1*gn1scale @ concat + b'), 64-col, direct fp16 in
// MODE 3: softmax(Wwc2*gn2scale @ x1p) * relu(gn3(y3h)) summed, 64-col
template <int MODE>
__global__ void __launch_bounds__(256, 2) hmma_k(Ptrs p) {
    constexpr bool DIRECT = (MODE >= 2);
    constexpr int COLS  = (MODE == 0) ? 128 : 64;
    constexpr int UNITS = B_ * (CPB / COLS);       // 4096 or 8192
    constexpr int SPM   = (MODE == 0) ? 132 : 68;  // stage row stride

    extern __shared__ char smem[];
    uint32_t* Bh0 = (uint32_t*)smem;
    uint32_t* Bh1 = Bh0 + COLS * LDB;              // DIRECT double buffer
    float* stage  = (float*)(Bh0 + COLS * LDB);    // !DIRECT
    const uint32_t stage_u = smem_to_u32(stage);
    const uint32_t bh0_u = smem_to_u32(Bh0);
    const uint32_t bh1_u = smem_to_u32(Bh1);

    const int tid = threadIdx.x;
    const int wid = tid >> 5, lane = tid & 31;
    const int lq = lane >> 2, lr = lane & 3;
    const int wrow = (MODE == 0) ? (wid >> 2) : (wid >> 1);
    const int wcol = (MODE == 0) ? (wid & 3) : (wid & 1);
    const int R0 = wrow * 32, C0 = wcol * 32;

    uint32_t aH[2][8][4];
    float biasv[2][2];
    biasv[0][0] = biasv[0][1] = biasv[1][0] = biasv[1][1] = 0.f;

    auto build_A = [&](int b) {
        constexpr int SLOT = (MODE == 2) ? 0 : 1;
#pragma unroll
        for (int mt = 0; mt < 2; ++mt) {
#pragma unroll
            for (int kk = 0; kk < 8; ++kk) {
                int kb = kk * 16 + lr * 2;
                float s0 = 1.f, s1 = 1.f, s2 = 1.f, s3 = 1.f;
                if (DIRECT) {
                    s0 = g_scale[SLOT][b][kb];
                    s1 = g_scale[SLOT][b][kb + 1];
                    s2 = g_scale[SLOT][b][kb + 8];
                    s3 = g_scale[SLOT][b][kb + 9];
                }
                const float* w0 = p.W + (R0 + mt * 16 + lq) * 128 + kb;
                const float* w1 = w0 + 8 * 128;
                float2 f0 = *(const float2*)(w0);
                float2 f1 = *(const float2*)(w1);
                float2 f2 = *(const float2*)(w0 + 8);
                float2 f3 = *(const float2*)(w1 + 8);
                aH[mt][kk][0] = packh(f0.x * s0, f0.y * s1);
                aH[mt][kk][1] = packh(f1.x * s0, f1.y * s1);
                aH[mt][kk][2] = packh(f2.x * s2, f2.y * s3);
                aH[mt][kk][3] = packh(f3.x * s2, f3.y * s3);
            }
        }
        if (MODE == 2) {
#pragma unroll
            for (int mt = 0; mt < 2; ++mt) {
                float a0 = 0.f, a1 = 0.f;
                for (int c = lr; c < 128; c += 4) {
                    float sh = g_shift[0][b][c];
                    a0 = fmaf(__ldg(p.W + (R0 + mt * 16 + lq) * 128 + c), sh, a0);
                    a1 = fmaf(__ldg(p.W + (R0 + mt * 16 + lq + 8) * 128 + c), sh, a1);
                }
                a0 += __shfl_xor_sync(0xffffffffu, a0, 1);
                a0 += __shfl_xor_sync(0xffffffffu, a0, 2);
                a1 += __shfl_xor_sync(0xffffffffu, a1, 1);
                a1 += __shfl_xor_sync(0xffffffffu, a1, 2);
                biasv[mt][0] = __ldg(p.bias + R0 + mt * 16 + lq) + a0;
                biasv[mt][1] = __ldg(p.bias + R0 + mt * 16 + lq + 8) + a1;
            }
        } else if (MODE != 3) {
#pragma unroll
            for (int mt = 0; mt < 2; ++mt) {
                biasv[mt][0] = __ldg(p.bias + R0 + mt * 16 + lq);
                biasv[mt][1] = __ldg(p.bias + R0 + mt * 16 + lq + 8);
            }
        }
    };

    auto unit_b   = [&](int u) { return (MODE == 0) ? (u >> 10) : (u >> 11); };
    auto unit_col = [&](int u) {
        if (MODE == 0) return (u & 1023) << 7;
        int h = u & 2047;
        return (h >> 1) * 128 + (h & 1) * 64;
    };

    auto load_stage = [&](int u) {           // modes 0/1 (fp32 input)
        int b = unit_b(u), colbase = unit_col(u);
        for (int idx = tid; idx < 128 * (COLS / 4); idx += 256) {
            int ch = idx / (COLS / 4), c4 = (idx % (COLS / 4)) << 2;
            cp_async16(stage_u + (uint32_t)(ch * SPM + c4) * 4u,
                       p.X + ((size_t)(b * 128 + ch)) * CPB + colbase + c4);
        }
        CP_COMMIT();
    };

    auto convert = [&]() {                    // stage fp32 -> Bh0 fp16
        for (int s = tid; s < COLS * 4; s += 256) {
            int col = s >> 2, r4 = s & 3;
#pragma unroll
            for (int j = 0; j < 16; ++j) {
                int k = r4 + 4 * j;
                int ch = 2 * k;
                float x0 = stage[ch * SPM + col];
                float x1 = stage[ch * SPM + SPM + col];
                Bh0[col * LDB + k] = packh(x0, x1);
            }
        }
    };

    auto load_direct = [&](int u, uint32_t bh_u) {   // modes 2/3, 64 cols
        int b = unit_b(u);
        int h = u & 2047, tt = h >> 1, half = h & 1;
        if (MODE == 3) {
            const uint32_t* base =
                x1p + ((size_t)(b * 1024 + tt) * 128 + half * 64) * 64;
            for (int idx = tid; idx < 1024; idx += 256) {
                int col = idx >> 4, chunk = idx & 15;
                cp_async16(bh_u + (uint32_t)(col * LDB + chunk * 4) * 4u,
                           base + col * 64 + chunk * 4);
            }
        } else {
            const uint32_t* gbase =
                g1p + ((size_t)(b * 1024 + tt) * 128 + half * 64) * 32;
            int colbase = tt * 128 + half * 64;
            for (int idx = tid; idx < 1024; idx += 256) {
                int col = idx >> 4, chunk = idx & 15;
                if (chunk < 8) {
                    int n = (colbase + col) >> 5;
                    cp_async16_ca(bh_u + (uint32_t)(col * LDB + chunk * 4) * 4u,
                                  &feat1p[b][n][chunk * 4]);
                } else {
                    cp_async16(bh_u + (uint32_t)(col * LDB + 32 + (chunk - 8) * 4) * 4u,
                               gbase + col * 32 + (chunk - 8) * 4);
                }
            }
        }
        CP_COMMIT();
    };

    auto run_tile = [&](uint32_t* Bcur, int u) {
        const int b = unit_b(u), colbase = unit_col(u);

        float D[2][4][4];
#pragma unroll
        for (int mt = 0; mt < 2; ++mt)
#pragma unroll
            for (int nt = 0; nt < 4; ++nt)
#pragma unroll
                for (int e = 0; e < 4; ++e) D[mt][nt][e] = 0.f;

#pragma unroll
        for (int kk = 0; kk < 8; ++kk) {
#pragma unroll
            for (int nt = 0; nt < 4; ++nt) {
                int n = C0 + nt * 8 + lq;
                uint32_t b0 = Bcur[n * LDB + kk * 8 + lr];
                uint32_t b1 = Bcur[n * LDB + kk * 8 + 4 + lr];
                MMA_F16(D[0][nt], aH[0][kk][0], aH[0][kk][1], aH[0][kk][2], aH[0][kk][3], b0, b1);
                MMA_F16(D[1][nt], aH[1][kk][0], aH[1][kk][1], aH[1][kk][2], aH[1][kk][3], b0, b1);
            }
        }

        if (MODE == 0 || MODE == 2) {
            constexpr int SLOT  = (MODE == 0) ? 0 : 1;
            constexpr int CHOFF = (MODE == 0) ? 64 : 0;
            constexpr int MST   = (MODE == 0) ? 32 : 64;
            uint32_t* gdst;
            if (MODE == 0) {
                gdst = g1p + ((size_t)(b * 1024 + (u & 1023)) * 128) * 32;
            } else {
                int h = u & 2047;
                gdst = x1p + ((size_t)(b * 1024 + (h >> 1)) * 128 + (h & 1) * 64) * 64;
            }
#pragma unroll
            for (int mt = 0; mt < 2; ++mt) {
#pragma unroll
                for (int half = 0; half < 2; ++half) {
                    int r = R0 + mt * 16 + lq + half * 8;
                    float bias = biasv[mt][half];
                    float s = 0.f, q = 0.f;
#pragma unroll
                    for (int nt = 0; nt < 4; ++nt) {
                        float v0 = fmaxf(D[mt][nt][half * 2 + 0] + bias, 0.f);
                        float v1 = fmaxf(D[mt][nt][half * 2 + 1] + bias, 0.f);
                        s += v0 + v1; q += v0 * v0 + v1 * v1;
                        float pv0 = __shfl_xor_sync(0xffffffffu, v0, 4);
                        float pv1 = __shfl_xor_sync(0xffffffffu, v1, 4);
                        if (!(lq & 1)) {
                            int col = C0 + nt * 8 + lr * 2;
                            int m = r >> 1;
                            gdst[(size_t)col * MST + m]       = packh(v0, pv0);
                            gdst[(size_t)(col + 1) * MST + m] = packh(v1, pv1);
                        }
                    }
                    s += __shfl_xor_sync(0xffffffffu, s, 1);
                    s += __shfl_xor_sync(0xffffffffu, s, 2);
                    q += __shfl_xor_sync(0xffffffffu, q, 1);
                    q += __shfl_xor_sync(0xffffffffu, q, 2);
                    if (lr == 0) {
                        atomicAdd(&g_sum[SLOT][b][CHOFF + r], (double)s);
                        atomicAdd(&g_sq [SLOT][b][CHOFF + r], (double)q);
                    }
                }
            }
        } else if (MODE == 1) {
#pragma unroll
            for (int mt = 0; mt < 2; ++mt) {
#pragma unroll
                for (int half = 0; half < 2; ++half) {
                    int r = R0 + mt * 16 + lq + half * 8;
                    float bias = biasv[mt][half];
                    float s = 0.f, q = 0.f;
                    __half* drow = y3h + (size_t)(b * 128 + r) * CPB + colbase + C0;
#pragma unroll
                    for (int nt = 0; nt < 4; ++nt) {
                        float v0 = D[mt][nt][half * 2 + 0] + bias;
                        float v1 = D[mt][nt][half * 2 + 1] + bias;
                        s += v0 + v1; q += v0 * v0 + v1 * v1;
                        *(uint32_t*)(drow + nt * 8 + lr * 2) = packh(v0, v1);
                    }
                    s += __shfl_xor_sync(0xffffffffu, s, 1);
                    s += __shfl_xor_sync(0xffffffffu, s, 2);
                    q += __shfl_xor_sync(0xffffffffu, q, 1);
                    q += __shfl_xor_sync(0xffffffffu, q, 2);
                    if (lr == 0) {
                        atomicAdd(&g_sum[2][b][r], (double)s);
                        atomicAdd(&g_sq [2][b][r], (double)q);
                    }
                }
            }
        } else { // MODE 3: one n per warp (C0 spans 32 cols = one n)
            int n = (colbase >> 5) + wcol;
            int cnt = __ldg(p.count + b * N_ + n);
            if (cnt < 1) cnt = 1;
#pragma unroll
            for (int mt = 0; mt < 2; ++mt) {
#pragma unroll
                for (int half = 0; half < 2; ++half) {
                    int c = R0 + mt * 16 + lq + half * 8;
                    float sc3 = g_scale[2][b][c], sh3 = g_shift[2][b][c];
                    float v[8];
                    float mx = -3.0e38f;
#pragma unroll
                    for (int nt = 0; nt < 4; ++nt) {
#pragma unroll
                        for (int e = 0; e < 2; ++e) {
                            int k = nt * 8 + lr * 2 + e;
                            float x = D[mt][nt][half * 2 + e];
                            x = (k < cnt) ? x : -1e9f;
                            v[nt * 2 + e] = x;
                            mx = fmaxf(mx, x);
                        }
                    }
                    mx = fmaxf(mx, __shfl_xor_sync(0xffffffffu, mx, 1));
                    mx = fmaxf(mx, __shfl_xor_sync(0xffffffffu, mx, 2));
                    const __half* yrow = y3h + (size_t)(b * 128 + c) * CPB + n * 32;
                    float num = 0.f, den = 0.f;
#pragma unroll
                    for (int nt = 0; nt < 4; ++nt) {
                        __half2 y2 = *(const __half2*)(yrow + nt * 8 + lr * 2);
                        float2 y = __half22float2(y2);
                        float e0 = __expf(v[nt * 2 + 0] - mx);
                        float e1 = __expf(v[nt * 2 + 1] - mx);
                        float g0 = fmaxf(fmaf(sc3, y.x, sh3), 0.f);
                        float g1 = fmaxf(fmaf(sc3, y.y, sh3), 0.f);
                        num += e0 * g0 + e1 * g1;
                        den += e0 + e1;
                    }
                    num += __shfl_xor_sync(0xffffffffu, num, 1);
                    num += __shfl_xor_sync(0xffffffffu, num, 2);
                    den += __shfl_xor_sync(0xffffffffu, den, 1);
                    den += __shfl_xor_sync(0xffffffffu, den, 2);
                    if (lr == 0)
                        p.out[(size_t)(b * 128 + c) * N_ + n] = num / den;
                }
            }
        }
    };

    // ---- main loops ----------------------------------------------------------
    const int G = gridDim.x;
    int cur_b = unit_b(blockIdx.x);
    build_A(cur_b);

    if (DIRECT) {
        load_direct(blockIdx.x, bh0_u);
        CP_WAIT0();
        __syncthreads();
        int cur = 0;
        for (int u = blockIdx.x; u < UNITS; u += G) {
            int b = unit_b(u);
            if (b != cur_b) { cur_b = b; build_A(b); }
            int un = u + G;
            if (un < UNITS) load_direct(un, cur ? bh0_u : bh1_u);
            run_tile(cur ? Bh1 : Bh0, u);
            CP_WAIT0();
            __syncthreads();
            cur ^= 1;
        }
    } else {
        load_stage(blockIdx.x);
        CP_WAIT0();
        __syncthreads();
        convert();
        __syncthreads();
        for (int u = blockIdx.x; u < UNITS; u += G) {
            int un = u + G;
            if (un < UNITS) load_stage(un);
            run_tile(Bh0, u);
            if (un < UNITS) {
                CP_WAIT0();
                __syncthreads();
                convert();
                __syncthreads();
            }
        }
    }
}

// ---------------------------------------------------------------------------
__global__ void finalize_k(int slot, const float* __restrict__ wgn,
                           const float* __restrict__ bgn) {
    int t = threadIdx.x;
    int b = t >> 7, c = t & 127;
    int g = (c >> 2) << 2;
    double s = g_sum[slot][b][g] + g_sum[slot][b][g + 1] +
               g_sum[slot][b][g + 2] + g_sum[slot][b][g + 3];
    double q = g_sq[slot][b][g] + g_sq[slot][b][g + 1] +
               g_sq[slot][b][g + 2] + g_sq[slot][b][g + 3];
    const double cnte = 4.0 * N_ * K_;
    double mu  = s / cnte;
    double var = q / cnte - mu * mu;
    float rstd = (float)(1.0 / sqrt(var + 1e-5));
    float sc   = wgn[c] * rstd;
    g_scale[slot][b][c] = sc;
    g_shift[slot][b][c] = bgn[c] - (float)mu * sc;
}

// ---------------------------------------------------------------------------
extern "C" void kernel_launch(void* const* d_in, const int* in_sizes, int n_in,
                              void* d_out, int out_size) {
    const float* feat   = (const float*)d_in[0];
    const float* gf     = (const float*)d_in[1];
    const float* gfo    = (const float*)d_in[2];
    const int*   count  = (const int*)  d_in[3];
    const float* W_feat = (const float*)d_in[4];
    const float* b_feat = (const float*)d_in[5];
    const float* W_grp  = (const float*)d_in[6];
    const float* b_grp  = (const float*)d_in[7];
    const float* gn1_w  = (const float*)d_in[8];
    const float* gn1_b  = (const float*)d_in[9];
    const float* W_wc1  = (const float*)d_in[10];
    const float* b_wc1  = (const float*)d_in[11];
    const float* gn2_w  = (const float*)d_in[12];
    const float* gn2_b  = (const float*)d_in[13];
    const float* W_wc2  = (const float*)d_in[14];
    const float* b_wc2  = (const float*)d_in[15];
    const float* W_fo   = (const float*)d_in[16];
    const float* b_fo   = (const float*)d_in[17];
    const float* gn3_w  = (const float*)d_in[18];
    const float* gn3_b  = (const float*)d_in[19];
    float* out = (float*)d_out;

    const int smem0 = 128 * LDB * 4 + 128 * 132 * 4;  // 102400
    const int smem1 = 64 * LDB * 4 + 128 * 68 * 4;    // 52224
    const int smemD = 2 * 64 * LDB * 4;               // 34816
    cudaFuncSetAttribute(hmma_k<0>, cudaFuncAttributeMaxDynamicSharedMemorySize, smem0);
    cudaFuncSetAttribute(hmma_k<1>, cudaFuncAttributeMaxDynamicSharedMemorySize, smem1);
    cudaFuncSetAttribute(hmma_k<2>, cudaFuncAttributeMaxDynamicSharedMemorySize, smemD);
    cudaFuncSetAttribute(hmma_k<3>, cudaFuncAttributeMaxDynamicSharedMemorySize, smemD);

    const int GRID = 296;   // 2 CTAs per SM

    zero_stats_k<<<2, 1024>>>();
    feat1_k<<<dim3(N_ / 32, B_), 256>>>(feat, W_feat, b_feat);

    { Ptrs p{gf,  W_grp, b_grp, nullptr, nullptr};
      hmma_k<0><<<GRID, 256, smem0>>>(p); }      // g1p + gn1 stats (ch 64+)
    { Ptrs p{gfo, W_fo,  b_fo,  nullptr, nullptr};
      hmma_k<1><<<GRID, 256, smem1>>>(p); }      // y3h + gn3 stats

    finalize_k<<<1, 512>>>(0, gn1_w, gn1_b);
    finalize_k<<<1, 512>>>(2, gn3_w, gn3_b);

    { Ptrs p{nullptr, W_wc1, b_wc1, nullptr, nullptr};
      hmma_k<2><<<GRID, 256, smemD>>>(p); }      // x1p + gn2 stats

    finalize_k<<<1, 512>>>(1, gn2_w, gn2_b);

    { Ptrs p{nullptr, W_wc2, b_wc2, count, out};
      hmma_k<3><<<GRID, 256, smemD>>>(p); }      // scores -> softmax -> out
}

// round 10
// speedup vs baseline: 1.3519x; 1.3519x over previous
#include <cuda_runtime.h>
#include <cuda_fp16.h>
#include <cstdint>
#include <cstddef>

// ---------------------------------------------------------------------------
constexpr int B_ = 4;
constexpr int N_ = 4096;
constexpr int K_ = 32;
constexpr int CPB = N_ * K_;              // 131072 columns per batch
constexpr int TPB = CPB / 128;            // 1024 full tiles per batch
constexpr int LDB = 68;                   // u32 stride per n-col of B tile

// ---------------------------------------------------------------------------
// Scratch: packed fp16 intermediates (B-fragment layout for direct cp.async)
// ---------------------------------------------------------------------------
__device__ uint32_t feat1p[B_][N_][32];                    //   2 MB
__device__ uint32_t g1p [(size_t)B_ * TPB * 128 * 32];     //  64 MB
__device__ uint32_t x1p [(size_t)B_ * TPB * 128 * 64];     // 128 MB
__device__ __half   y3h [(size_t)B_ * 128 * CPB];          // 128 MB

__device__ double g_sum  [3][B_][128];
__device__ double g_sq   [3][B_][128];
__device__ float  g_scale[3][B_][128];
__device__ float  g_shift[3][B_][128];

// ---------------------------------------------------------------------------
__device__ __forceinline__ uint32_t smem_to_u32(const void* p) {
    uint32_t a;
    asm("{ .reg .u64 t; cvta.to.shared.u64 t, %1; cvt.u32.u64 %0, t; }"
        : "=r"(a) : "l"(p));
    return a;
}
__device__ __forceinline__ void cp_async16(uint32_t dst, const void* src) {
    asm volatile("cp.async.cg.shared.global [%0], [%1], 16;" :: "r"(dst), "l"(src));
}
__device__ __forceinline__ void cp_async16_ca(uint32_t dst, const void* src) {
    asm volatile("cp.async.ca.shared.global [%0], [%1], 16;" :: "r"(dst), "l"(src));
}
#define CP_COMMIT() asm volatile("cp.async.commit_group;" ::: "memory")
#define CP_WAIT0()  asm volatile("cp.async.wait_group 0;" ::: "memory")
#define CP_WAIT1()  asm volatile("cp.async.wait_group 1;" ::: "memory")

#define MMA_F16(d, a0, a1, a2, a3, b0, b1) \
    asm volatile("mma.sync.aligned.m16n8k16.row.col.f32.f16.f16.f32 " \
        "{%0,%1,%2,%3},{%4,%5,%6,%7},{%8,%9},{%0,%1,%2,%3};" \
        : "+f"((d)[0]), "+f"((d)[1]), "+f"((d)[2]), "+f"((d)[3]) \
        : "r"(a0), "r"(a1), "r"(a2), "r"(a3), "r"(b0), "r"(b1))

__device__ __forceinline__ uint32_t packh(float x0, float x1) {
    __half2 h = __float22half2_rn(make_float2(x0, x1));
    return *(uint32_t*)&h;
}
__device__ __forceinline__ void splith(float x0, float x1, uint32_t& hi, uint32_t& lo) {
    __half2 h = __float22half2_rn(make_float2(x0, x1));
    float2 hf = __half22float2(h);
    __half2 l = __float22half2_rn(make_float2(x0 - hf.x, x1 - hf.y));
    hi = *(uint32_t*)&h;
    lo = *(uint32_t*)&l;
}

// ---------------------------------------------------------------------------
__global__ void zero_stats_k() {
    int t = blockIdx.x * blockDim.x + threadIdx.x;
    if (t < 3 * B_ * 128) {
        (&g_sum[0][0][0])[t] = 0.0;
        (&g_sq [0][0][0])[t] = 0.0;
    }
}

// ---------------------------------------------------------------------------
// feat1 = relu(W_feat @ feat + b): packed fp16 into feat1p + gn1 stats (ch<64)
// ---------------------------------------------------------------------------
__global__ void __launch_bounds__(256) feat1_k(const float* __restrict__ feat,
                                               const float* __restrict__ Wf,
                                               const float* __restrict__ bf) {
    __shared__ float Ws[64 * 128];
    __shared__ float Fs[128 * 32];
    const int b  = blockIdx.y;
    const int n0 = blockIdx.x * 32;
    const int tid = threadIdx.x;

    for (int idx = tid; idx < 64 * 128; idx += 256) Ws[idx] = Wf[idx];
    for (int idx = tid; idx < 128 * 32; idx += 256) {
        int c = idx >> 5, jj = idx & 31;
        Fs[idx] = feat[(size_t)(b * 128 + c) * N_ + n0 + jj];
    }
    __syncthreads();

    const int jj = tid & 31;
    const int w  = tid >> 5;
    float acc[8];
#pragma unroll
    for (int oi = 0; oi < 8; ++oi) acc[oi] = __ldg(bf + w * 8 + oi);
#pragma unroll 4
    for (int c = 0; c < 128; ++c) {
        float x = Fs[c * 32 + jj];
#pragma unroll
        for (int oi = 0; oi < 8; ++oi)
            acc[oi] = fmaf(Ws[(w * 8 + oi) * 128 + c], x, acc[oi]);
    }
#pragma unroll
    for (int oi = 0; oi < 8; ++oi) acc[oi] = fmaxf(acc[oi], 0.f);

#pragma unroll
    for (int oi = 0; oi < 8; ++oi) {
        float s = acc[oi], q = acc[oi] * acc[oi];
#pragma unroll
        for (int off = 16; off; off >>= 1) {
            s += __shfl_xor_sync(0xffffffffu, s, off);
            q += __shfl_xor_sync(0xffffffffu, q, off);
        }
        if (jj == 0) {
            atomicAdd(&g_sum[0][b][w * 8 + oi], (double)(32.0f * s));
            atomicAdd(&g_sq [0][b][w * 8 + oi], (double)(32.0f * q));
        }
    }
    uint4 pk;
    pk.x = packh(acc[0], acc[1]);
    pk.y = packh(acc[2], acc[3]);
    pk.z = packh(acc[4], acc[5]);
    pk.w = packh(acc[6], acc[7]);
    *(uint4*)&feat1p[b][n0 + jj][w * 4] = pk;
}

// ---------------------------------------------------------------------------
struct Ptrs {
    const float* X;
    const float* W;
    const float* bias;
    const int*   count;
    float*       out;
};

// MODE 0: g1p = relu(W_grp@gf+b), 128-col tiles, single-buffer pipeline
// MODE 1: y3h = W_fo@gfo+b, 64-col tiles, SPLIT A, 2-deep stage pipeline
// MODE 2: x1p = relu(Wwc1*gn1scale @ concat + b'), 64-col, 2-deep direct
// MODE 3: softmax(Wwc2*gn2scale @ x1p) * relu(gn3(y3h)) summed, 2-deep direct
template <int MODE>
__global__ void __launch_bounds__(256, 2) hmma_k(Ptrs p) {
    constexpr bool DIRECT = (MODE >= 2);
    constexpr bool SPLIT  = (MODE == 1);
    constexpr int COLS  = (MODE == 0) ? 128 : 64;
    constexpr int UNITS = B_ * (CPB / COLS);       // 4096 or 8192
    constexpr int SPM   = (MODE == 0) ? 132 : 68;  // stage row stride
    constexpr int NB    = (MODE == 0) ? 1 : ((MODE == 1) ? 2 : 3);

    extern __shared__ char smem[];
    uint32_t* BhBuf = (uint32_t*)smem;                 // NB buffers of COLS*LDB
    float* stBuf    = (float*)(BhBuf + NB * COLS * LDB); // modes 0/1 stage(s)

    const int tid = threadIdx.x;
    const int wid = tid >> 5, lane = tid & 31;
    const int lq = lane >> 2, lr = lane & 3;
    const int wrow = (MODE == 0) ? (wid >> 1) : wid;
    const int wcol = (MODE == 0) ? (wid & 1) : 0;
    const int R0 = wrow * 16;
    const int C0 = wcol * 64;

    uint32_t aH[8][4];
    uint32_t aL[SPLIT ? 8 : 1][4];
    float bias0 = 0.f, bias1 = 0.f;

    auto build_A = [&](int b) {
        constexpr int SLOT = (MODE == 2) ? 0 : 1;
#pragma unroll
        for (int kk = 0; kk < 8; ++kk) {
            int kb = kk * 16 + lr * 2;
            float s0 = 1.f, s1 = 1.f, s2 = 1.f, s3 = 1.f;
            if (DIRECT) {
                s0 = g_scale[SLOT][b][kb];
                s1 = g_scale[SLOT][b][kb + 1];
                s2 = g_scale[SLOT][b][kb + 8];
                s3 = g_scale[SLOT][b][kb + 9];
            }
            const float* w0 = p.W + (R0 + lq) * 128 + kb;
            const float* w1 = p.W + (R0 + lq + 8) * 128 + kb;
            float2 f0 = *(const float2*)(w0);
            float2 f1 = *(const float2*)(w1);
            float2 f2 = *(const float2*)(w0 + 8);
            float2 f3 = *(const float2*)(w1 + 8);
            if (SPLIT) {
                splith(f0.x * s0, f0.y * s1, aH[kk][0], aL[SPLIT ? kk : 0][0]);
                splith(f1.x * s0, f1.y * s1, aH[kk][1], aL[SPLIT ? kk : 0][1]);
                splith(f2.x * s2, f2.y * s3, aH[kk][2], aL[SPLIT ? kk : 0][2]);
                splith(f3.x * s2, f3.y * s3, aH[kk][3], aL[SPLIT ? kk : 0][3]);
            } else {
                aH[kk][0] = packh(f0.x * s0, f0.y * s1);
                aH[kk][1] = packh(f1.x * s0, f1.y * s1);
                aH[kk][2] = packh(f2.x * s2, f2.y * s3);
                aH[kk][3] = packh(f3.x * s2, f3.y * s3);
            }
        }
        if (MODE == 2) {
            float a0 = 0.f, a1 = 0.f;
            for (int c = lr; c < 128; c += 4) {
                float sh = g_shift[0][b][c];
                a0 = fmaf(__ldg(p.W + (R0 + lq) * 128 + c), sh, a0);
                a1 = fmaf(__ldg(p.W + (R0 + lq + 8) * 128 + c), sh, a1);
            }
            a0 += __shfl_xor_sync(0xffffffffu, a0, 1);
            a0 += __shfl_xor_sync(0xffffffffu, a0, 2);
            a1 += __shfl_xor_sync(0xffffffffu, a1, 1);
            a1 += __shfl_xor_sync(0xffffffffu, a1, 2);
            bias0 = __ldg(p.bias + R0 + lq) + a0;
            bias1 = __ldg(p.bias + R0 + lq + 8) + a1;
        } else if (MODE != 3) {
            bias0 = __ldg(p.bias + R0 + lq);
            bias1 = __ldg(p.bias + R0 + lq + 8);
        }
    };

    auto unit_b   = [&](int u) { return (MODE == 0) ? (u >> 10) : (u >> 11); };
    auto unit_col = [&](int u) {
        if (MODE == 0) return (u & 1023) << 7;
        int h = u & 2047;
        return (h >> 1) * 128 + (h & 1) * 64;
    };

    auto load_stage = [&](int u, float* st) {       // modes 0/1 (fp32 input)
        uint32_t st_u = smem_to_u32(st);
        int b = unit_b(u), colbase = unit_col(u);
        for (int idx = tid; idx < 128 * (COLS / 4); idx += 256) {
            int ch = idx / (COLS / 4), c4 = (idx % (COLS / 4)) << 2;
            cp_async16(st_u + (uint32_t)(ch * SPM + c4) * 4u,
                       p.X + ((size_t)(b * 128 + ch)) * CPB + colbase + c4);
        }
        CP_COMMIT();
    };

    auto convert = [&](const float* st, uint32_t* Bdst) {  // fp32 -> fp16
        for (int s = tid; s < COLS * 4; s += 256) {
            int col = s >> 2, r4 = s & 3;
#pragma unroll
            for (int j = 0; j < 16; ++j) {
                int k = r4 + 4 * j;
                int ch = 2 * k;
                float x0 = st[ch * SPM + col];
                float x1 = st[ch * SPM + SPM + col];
                Bdst[col * LDB + k] = packh(x0, x1);
            }
        }
    };

    auto load_direct = [&](int u, uint32_t* Bdst) {   // modes 2/3, 64 cols
        uint32_t bh_u = smem_to_u32(Bdst);
        int b = unit_b(u);
        int h = u & 2047, tt = h >> 1, half = h & 1;
        if (MODE == 3) {
            const uint32_t* base =
                x1p + ((size_t)(b * 1024 + tt) * 128 + half * 64) * 64;
            for (int idx = tid; idx < 1024; idx += 256) {
                int col = idx >> 4, chunk = idx & 15;
                cp_async16(bh_u + (uint32_t)(col * LDB + chunk * 4) * 4u,
                           base + col * 64 + chunk * 4);
            }
        } else {
            const uint32_t* gbase =
                g1p + ((size_t)(b * 1024 + tt) * 128 + half * 64) * 32;
            int colbase = tt * 128 + half * 64;
            for (int idx = tid; idx < 1024; idx += 256) {
                int col = idx >> 4, chunk = idx & 15;
                if (chunk < 8) {
                    int n = (colbase + col) >> 5;
                    cp_async16_ca(bh_u + (uint32_t)(col * LDB + chunk * 4) * 4u,
                                  &feat1p[b][n][chunk * 4]);
                } else {
                    cp_async16(bh_u + (uint32_t)(col * LDB + 32 + (chunk - 8) * 4) * 4u,
                               gbase + col * 32 + (chunk - 8) * 4);
                }
            }
        }
        CP_COMMIT();
    };

    auto run_tile = [&](uint32_t* Bcur, int u) {
        const int b = unit_b(u), colbase = unit_col(u);

        float D[8][4];
#pragma unroll
        for (int nt = 0; nt < 8; ++nt)
#pragma unroll
            for (int e = 0; e < 4; ++e) D[nt][e] = 0.f;

#pragma unroll
        for (int kk = 0; kk < 8; ++kk) {
#pragma unroll
            for (int nt = 0; nt < 8; ++nt) {
                int n = C0 + nt * 8 + lq;
                uint32_t b0 = Bcur[n * LDB + kk * 8 + lr];
                uint32_t b1 = Bcur[n * LDB + kk * 8 + 4 + lr];
                MMA_F16(D[nt], aH[kk][0], aH[kk][1], aH[kk][2], aH[kk][3], b0, b1);
                if (SPLIT)
                    MMA_F16(D[nt], aL[SPLIT ? kk : 0][0], aL[SPLIT ? kk : 0][1],
                            aL[SPLIT ? kk : 0][2], aL[SPLIT ? kk : 0][3], b0, b1);
            }
        }

        if (MODE == 0 || MODE == 2) {
            constexpr int SLOT  = (MODE == 0) ? 0 : 1;
            constexpr int CHOFF = (MODE == 0) ? 64 : 0;
            constexpr int MST   = (MODE == 0) ? 32 : 64;
            uint32_t* gdst;
            if (MODE == 0) {
                gdst = g1p + ((size_t)(b * 1024 + (u & 1023)) * 128) * 32;
            } else {
                int h = u & 2047;
                gdst = x1p + ((size_t)(b * 1024 + (h >> 1)) * 128 + (h & 1) * 64) * 64;
            }
#pragma unroll
            for (int half = 0; half < 2; ++half) {
                int r = R0 + lq + half * 8;
                float bias = half ? bias1 : bias0;
                int m = (R0 >> 1) + (lq >> 1) + 4 * half;
                float s = 0.f, q = 0.f;
#pragma unroll
                for (int nt = 0; nt < 8; ++nt) {
                    float v0 = fmaxf(D[nt][half * 2 + 0] + bias, 0.f);
                    float v1 = fmaxf(D[nt][half * 2 + 1] + bias, 0.f);
                    s += v0 + v1; q += v0 * v0 + v1 * v1;
                    float pv0 = __shfl_xor_sync(0xffffffffu, v0, 4);
                    float pv1 = __shfl_xor_sync(0xffffffffu, v1, 4);
                    if (!(lq & 1)) {
                        int col = C0 + nt * 8 + lr * 2;
                        gdst[(size_t)col * MST + m]       = packh(v0, pv0);
                        gdst[(size_t)(col + 1) * MST + m] = packh(v1, pv1);
                    }
                }
                s += __shfl_xor_sync(0xffffffffu, s, 1);
                s += __shfl_xor_sync(0xffffffffu, s, 2);
                q += __shfl_xor_sync(0xffffffffu, q, 1);
                q += __shfl_xor_sync(0xffffffffu, q, 2);
                if (lr == 0) {
                    atomicAdd(&g_sum[SLOT][b][CHOFF + r], (double)s);
                    atomicAdd(&g_sq [SLOT][b][CHOFF + r], (double)q);
                }
            }
        } else if (MODE == 1) {
#pragma unroll
            for (int half = 0; half < 2; ++half) {
                int r = R0 + lq + half * 8;
                float bias = half ? bias1 : bias0;
                float s = 0.f, q = 0.f;
                __half* drow = y3h + (size_t)(b * 128 + r) * CPB + colbase;
#pragma unroll
                for (int nt = 0; nt < 8; ++nt) {
                    float v0 = D[nt][half * 2 + 0] + bias;
                    float v1 = D[nt][half * 2 + 1] + bias;
                    s += v0 + v1; q += v0 * v0 + v1 * v1;
                    *(uint32_t*)(drow + nt * 8 + lr * 2) = packh(v0, v1);
                }
                s += __shfl_xor_sync(0xffffffffu, s, 1);
                s += __shfl_xor_sync(0xffffffffu, s, 2);
                q += __shfl_xor_sync(0xffffffffu, q, 1);
                q += __shfl_xor_sync(0xffffffffu, q, 2);
                if (lr == 0) {
                    atomicAdd(&g_sum[2][b][r], (double)s);
                    atomicAdd(&g_sq [2][b][r], (double)q);
                }
            }
        } else { // MODE 3
#pragma unroll
            for (int half = 0; half < 2; ++half) {
                int c = R0 + lq + half * 8;
                float sc3 = g_scale[2][b][c], sh3 = g_shift[2][b][c];
#pragma unroll
                for (int ni = 0; ni < 2; ++ni) {
                    int n = (colbase >> 5) + ni;
                    int cnt = __ldg(p.count + b * N_ + n);
                    if (cnt < 1) cnt = 1;
                    float v[8];
                    float mx = -3.0e38f;
#pragma unroll
                    for (int nt2 = 0; nt2 < 4; ++nt2) {
#pragma unroll
                        for (int e = 0; e < 2; ++e) {
                            int k = nt2 * 8 + lr * 2 + e;
                            float x = D[ni * 4 + nt2][half * 2 + e];
                            x = (k < cnt) ? x : -1e9f;
                            v[nt2 * 2 + e] = x;
                            mx = fmaxf(mx, x);
                        }
                    }
                    mx = fmaxf(mx, __shfl_xor_sync(0xffffffffu, mx, 1));
                    mx = fmaxf(mx, __shfl_xor_sync(0xffffffffu, mx, 2));
                    const __half* yrow = y3h + (size_t)(b * 128 + c) * CPB + n * 32;
                    float num = 0.f, den = 0.f;
#pragma unroll
                    for (int nt2 = 0; nt2 < 4; ++nt2) {
                        __half2 y2 = *(const __half2*)(yrow + nt2 * 8 + lr * 2);
                        float2 y = __half22float2(y2);
                        float e0 = __expf(v[nt2 * 2 + 0] - mx);
                        float e1 = __expf(v[nt2 * 2 + 1] - mx);
                        float g0 = fmaxf(fmaf(sc3, y.x, sh3), 0.f);
                        float g1 = fmaxf(fmaf(sc3, y.y, sh3), 0.f);
                        num += e0 * g0 + e1 * g1;
                        den += e0 + e1;
                    }
                    num += __shfl_xor_sync(0xffffffffu, num, 1);
                    num += __shfl_xor_sync(0xffffffffu, num, 2);
                    den += __shfl_xor_sync(0xffffffffu, den, 1);
                    den += __shfl_xor_sync(0xffffffffu, den, 2);
                    if (lr == 0)
                        p.out[(size_t)(b * 128 + c) * N_ + n] = num / den;
                }
            }
        }
    };

    // ---- main loops ----------------------------------------------------------
    const int G = gridDim.x;
    const int u0 = blockIdx.x;
    int cur_b = unit_b(u0);
    build_A(cur_b);

    if (MODE >= 2) {
        // DIRECT: 3 Bh buffers, 2 cp.async groups in flight
        uint32_t* Bh[3] = {BhBuf, BhBuf + COLS * LDB, BhBuf + 2 * COLS * LDB};
        load_direct(u0, Bh[0]);
        bool have1 = (u0 + G < UNITS);
        if (have1) load_direct(u0 + G, Bh[1]);
        if (have1) { CP_WAIT1(); } else { CP_WAIT0(); }
        __syncthreads();
        int i = 0;
        for (int u = u0; u < UNITS; u += G, i = (i + 1) % 3) {
            int b = unit_b(u);
            if (b != cur_b) { cur_b = b; build_A(b); }
            bool have2 = (u + 2 * G < UNITS);
            if (have2) load_direct(u + 2 * G, Bh[(i + 2) % 3]);
            run_tile(Bh[i], u);
            if (u + G < UNITS) {
                if (have2) { CP_WAIT1(); } else { CP_WAIT0(); }
                __syncthreads();
            }
        }
    } else if (MODE == 1) {
        // 2-deep stage pipeline: 2 stages + 2 Bh
        uint32_t* Bh[2] = {BhBuf, BhBuf + COLS * LDB};
        float* st[2] = {stBuf, stBuf + 128 * SPM};
        load_stage(u0, st[0]);
        bool have1 = (u0 + G < UNITS);
        if (have1) load_stage(u0 + G, st[1]);
        if (have1) { CP_WAIT1(); } else { CP_WAIT0(); }
        __syncthreads();
        convert(st[0], Bh[0]);
        __syncthreads();
        int i = 0;
        for (int u = u0; u < UNITS; u += G, i ^= 1) {
            bool have2 = (u + 2 * G < UNITS);
            if (have2) load_stage(u + 2 * G, st[i]);
            run_tile(Bh[i], u);
            if (u + G < UNITS) {
                if (have2) { CP_WAIT1(); } else { CP_WAIT0(); }
                __syncthreads();
                convert(st[i ^ 1], Bh[i ^ 1]);
                __syncthreads();
            }
        }
    } else {
        // MODE 0: single-buffer pipeline (round-8 behavior)
        uint32_t* Bh0 = BhBuf;
        float* st0 = stBuf;
        load_stage(u0, st0);
        CP_WAIT0();
        __syncthreads();
        convert(st0, Bh0);
        __syncthreads();
        for (int u = u0; u < UNITS; u += G) {
            int un = u + G;
            if (un < UNITS) load_stage(un, st0);
            run_tile(Bh0, u);
            if (un < UNITS) {
                CP_WAIT0();
                __syncthreads();
                convert(st0, Bh0);
                __syncthreads();
            }
        }
    }
}

// ---------------------------------------------------------------------------
__global__ void finalize_k(int slot, const float* __restrict__ wgn,
                           const float* __restrict__ bgn) {
    int t = threadIdx.x;
    int b = t >> 7, c = t & 127;
    int g = (c >> 2) << 2;
    double s = g_sum[slot][b][g] + g_sum[slot][b][g + 1] +
               g_sum[slot][b][g + 2] + g_sum[slot][b][g + 3];
    double q = g_sq[slot][b][g] + g_sq[slot][b][g + 1] +
               g_sq[slot][b][g + 2] + g_sq[slot][b][g + 3];
    const double cnte = 4.0 * N_ * K_;
    double mu  = s / cnte;
    double var = q / cnte - mu * mu;
    float rstd = (float)(1.0 / sqrt(var + 1e-5));
    float sc   = wgn[c] * rstd;
    g_scale[slot][b][c] = sc;
    g_shift[slot][b][c] = bgn[c] - (float)mu * sc;
}

// ---------------------------------------------------------------------------
extern "C" void kernel_launch(void* const* d_in, const int* in_sizes, int n_in,
                              void* d_out, int out_size) {
    const float* feat   = (const float*)d_in[0];
    const float* gf     = (const float*)d_in[1];
    const float* gfo    = (const float*)d_in[2];
    const int*   count  = (const int*)  d_in[3];
    const float* W_feat = (const float*)d_in[4];
    const float* b_feat = (const float*)d_in[5];
    const float* W_grp  = (const float*)d_in[6];
    const float* b_grp  = (const float*)d_in[7];
    const float* gn1_w  = (const float*)d_in[8];
    const float* gn1_b  = (const float*)d_in[9];
    const float* W_wc1  = (const float*)d_in[10];
    const float* b_wc1  = (const float*)d_in[11];
    const float* gn2_w  = (const float*)d_in[12];
    const float* gn2_b  = (const float*)d_in[13];
    const float* W_wc2  = (const float*)d_in[14];
    const float* b_wc2  = (const float*)d_in[15];
    const float* W_fo   = (const float*)d_in[16];
    const float* b_fo   = (const float*)d_in[17];
    const float* gn3_w  = (const float*)d_in[18];
    const float* gn3_b  = (const float*)d_in[19];
    float* out = (float*)d_out;

    const int smem0 = 128 * LDB * 4 + 128 * 132 * 4;        // 102400
    const int smem1 = 2 * 64 * LDB * 4 + 2 * 128 * 68 * 4;  // 34816+69632=104448
    const int smemD = 3 * 64 * LDB * 4;                     // 52224
    cudaFuncSetAttribute(hmma_k<0>, cudaFuncAttributeMaxDynamicSharedMemorySize, smem0);
    cudaFuncSetAttribute(hmma_k<1>, cudaFuncAttributeMaxDynamicSharedMemorySize, smem1);
    cudaFuncSetAttribute(hmma_k<2>, cudaFuncAttributeMaxDynamicSharedMemorySize, smemD);
    cudaFuncSetAttribute(hmma_k<3>, cudaFuncAttributeMaxDynamicSharedMemorySize, smemD);

    const int GRID = 296;   // 2 CTAs per SM

    zero_stats_k<<<2, 1024>>>();
    feat1_k<<<dim3(N_ / 32, B_), 256>>>(feat, W_feat, b_feat);

    { Ptrs p{gf,  W_grp, b_grp, nullptr, nullptr};
      hmma_k<0><<<GRID, 256, smem0>>>(p); }      // g1p + gn1 stats (ch 64+)
    { Ptrs p{gfo, W_fo,  b_fo,  nullptr, nullptr};
      hmma_k<1><<<GRID, 256, smem1>>>(p); }      // y3h + gn3 stats

    finalize_k<<<1, 512>>>(0, gn1_w, gn1_b);
    finalize_k<<<1, 512>>>(2, gn3_w, gn3_b);

    { Ptrs p{nullptr, W_wc1, b_wc1, nullptr, nullptr};
      hmma_k<2><<<GRID, 256, smemD>>>(p); }      // x1p + gn2 stats

    finalize_k<<<1, 512>>>(1, gn2_w, gn2_b);

    { Ptrs p{nullptr, W_wc2, b_wc2, count, out};
      hmma_k<3><<<GRID, 256, smemD>>>(p); }      // scores -> softmax -> out
}